// round 15
// baseline (speedup 1.0000x reference)
#include <cuda_runtime.h>
#include <cuda_fp16.h>
#include <cstdint>
#include <cstddef>

// ============================================================================
// Static device scratch (allocation-free rule: __device__ globals)
// ============================================================================
#define MAXD 4096
__device__ __half g_xh[(size_t)MAXD * MAXD];   // x in fp16
__device__ __half g_q[(size_t)MAXD * MAXD];    // E8 lattice points q (exact in fp16)
__device__ float  g_scale[MAXD];               // row_norm_safe / sf

// ============================================================================
// PTX helpers (baseline sm_100: cp.async + ldmatrix + mma.sync)
// ============================================================================
static __device__ __forceinline__ uint32_t smem_u32(const void* p) {
    return (uint32_t)__cvta_generic_to_shared(p);
}
static __device__ __forceinline__ void cp_async16(uint32_t dst, const void* src) {
    asm volatile("cp.async.cg.shared.global [%0], [%1], 16;" :: "r"(dst), "l"(src));
}
static __device__ __forceinline__ void cp_commit() {
    asm volatile("cp.async.commit_group;");
}
template <int N>
static __device__ __forceinline__ void cp_wait() {
    asm volatile("cp.async.wait_group %0;" :: "n"(N));
}

#define LDSM4(R, addr) \
    asm volatile("ldmatrix.sync.aligned.m8n8.x4.shared.b16 {%0,%1,%2,%3}, [%4];" \
                 : "=r"((R)[0]), "=r"((R)[1]), "=r"((R)[2]), "=r"((R)[3]) : "r"(addr))

#define MMA16816(C, A, b0, b1) \
    asm volatile("mma.sync.aligned.m16n8k16.row.col.f32.f16.f16.f32 " \
                 "{%0,%1,%2,%3}, {%4,%5,%6,%7}, {%8,%9}, {%0,%1,%2,%3};" \
                 : "+f"((C)[0]), "+f"((C)[1]), "+f"((C)[2]), "+f"((C)[3]) \
                 : "r"((A)[0]), "r"((A)[1]), "r"((A)[2]), "r"((A)[3]), \
                   "r"(b0), "r"(b1))

// ============================================================================
// E8 lattice quantization (exactly matches the JAX reference semantics)
// ============================================================================
static __device__ __forceinline__ void nearest_d8(const float x[8], float y[8]) {
    float f[8], d[8];
    float s = 0.f;
#pragma unroll
    for (int i = 0; i < 8; i++) { f[i] = rintf(x[i]); d[i] = x[i] - f[i]; s += f[i]; }
    int odd = (int)(((long long)llrintf(s)) & 1);
    float amax = -1.f; int idx = 0;
#pragma unroll
    for (int i = 0; i < 8; i++) {
        float a = fabsf(d[i]);
        if (a > amax) { amax = a; idx = i; }   // strict > keeps FIRST max (jnp.argmax)
    }
#pragma unroll
    for (int i = 0; i < 8; i++) {
        float flip = (odd && (i == idx)) ? ((d[i] >= 0.f) ? 1.f : -1.f) : 0.f;
        y[i] = f[i] + flip;
    }
}

static __device__ __forceinline__ void e8_quant(const float x[8], float y[8]) {
    float y0[8], y1[8], xs[8];
    nearest_d8(x, y0);
#pragma unroll
    for (int i = 0; i < 8; i++) xs[i] = x[i] - 0.5f;
    nearest_d8(xs, y1);
#pragma unroll
    for (int i = 0; i < 8; i++) y1[i] += 0.5f;
    float d0 = 0.f, d1 = 0.f;
#pragma unroll
    for (int i = 0; i < 8; i++) {
        float a = x[i] - y0[i]; d0 += a * a;
        float b = x[i] - y1[i]; d1 += b * b;
    }
#pragma unroll
    for (int i = 0; i < 8; i++) y[i] = (d0 <= d1) ? y0[i] : y1[i];
}

// ============================================================================
// Fused prep kernel:
//   blocks [0, OUT)        : row norm (fp32 warp-reduce) + E8 quantize
//   blocks [OUT, OUT+XB)   : x (fp32) -> fp16 into g_xh
// ============================================================================
#define XB 512

__global__ void prep_fused_kernel(const float* __restrict__ x, int nx,
                                  const float* __restrict__ w, int IN, int OUT,
                                  float sf)
{
    if ((int)blockIdx.x >= OUT) {
        const int xb = blockIdx.x - OUT;
        int i = xb * blockDim.x + threadIdx.x;
        const int stride = XB * blockDim.x;
        const int n2 = nx >> 1;
        for (; i < n2; i += stride) {
            float2 v = ((const float2*)x)[i];
            ((__half2*)g_xh)[i] = __floats2half2_rn(v.x, v.y);
        }
        return;
    }

    const int row = blockIdx.x;
    const float* wr = w + (size_t)row * IN;
    __shared__ float redf[8];
    __shared__ float s_inv;
    float part = 0.f;
    for (int i = threadIdx.x * 4; i < IN; i += blockDim.x * 4) {
        float4 t = *(const float4*)(wr + i);
        part += t.x * t.x + t.y * t.y + t.z * t.z + t.w * t.w;
    }
#pragma unroll
    for (int o = 16; o; o >>= 1) part += __shfl_xor_sync(0xffffffffu, part, o);
    if ((threadIdx.x & 31) == 0) redf[threadIdx.x >> 5] = part;
    __syncthreads();
    if (threadIdx.x == 0) {
        float t = 0.f;
        for (int i = 0; i < (int)(blockDim.x >> 5); i++) t += redf[i];
        float rn = sqrtf(t);
        rn = fmaxf(rn, 1e-8f);
        s_inv = sf / rn;               // one divide per row
        g_scale[row] = rn / sf;
    }
    __syncthreads();
    const float inv = s_inv;
    __half* qrow = g_q + (size_t)row * IN;
    const int nblk = IN >> 3;
    for (int b = threadIdx.x; b < nblk; b += blockDim.x) {
        float v[8], y[8];
#pragma unroll
        for (int j = 0; j < 8; j++) v[j] = wr[b * 8 + j] * inv;
        e8_quant(v, y);
#pragma unroll
        for (int j = 0; j < 8; j++) qrow[b * 8 + j] = __float2half_rn(y[j]);  // exact
    }
}

// ============================================================================
// GEMM: out[M,N] = (x_fp16 @ q^T) * scale[n] + bias[n]
// BM=BN=128, BK=64, 256 threads (2x4 warps, 64x32 warp tiles), STAGES=3,
// 96KB smem/CTA -> 2 CTAs/SM. Key ordering: ks0 ldmatrix issues BEFORE the
// next stage's cp.async burst, so the critical LDSM isn't queued behind
// 128 LDGSTS ops in the LSU at each kt boundary.
// ============================================================================
#define BM 128
#define BN 128
#define BK 64
#define NT 256
#define STAGES 3
#define A_BYTES (BM * 128)                  // 16384
#define B_BYTES (BN * 128)                  // 16384
#define STAGE_BYTES (A_BYTES + B_BYTES)     // 32768
#define SMEM_TOTAL (STAGES * STAGE_BYTES)   // 98304

static __device__ __forceinline__ void load_stage(
    uint32_t sb, int s, int kt, int tid,
    const __half* gA, const __half* gB, int K)
{
    const int kc = kt * BK;                  // halves
    const uint32_t a = sb + (uint32_t)s * STAGE_BYTES;
    const uint32_t b = a + A_BYTES;
#pragma unroll
    for (int i = 0; i < (BM * 8) / NT; i++) {       // 4 iters
        int idx = tid + i * NT;
        int r = idx >> 3, cc = idx & 7;
        uint32_t off = (uint32_t)(r * 128 + (((uint32_t)cc ^ (uint32_t)(r & 7)) << 4));
        cp_async16(a + off, (const char*)(gA + (size_t)r * K + kc) + (cc << 4));
    }
#pragma unroll
    for (int i = 0; i < (BN * 8) / NT; i++) {       // 4 iters
        int idx = tid + i * NT;
        int r = idx >> 3, cc = idx & 7;
        uint32_t off = (uint32_t)(r * 128 + (((uint32_t)cc ^ (uint32_t)(r & 7)) << 4));
        cp_async16(b + off, (const char*)(gB + (size_t)r * K + kc) + (cc << 4));
    }
}

static __device__ __forceinline__ void lds_frags(
    uint32_t sb, int s, int ks, int warp_m, int warp_n, int lane,
    uint32_t A[4][4], uint32_t B[2][4])
{
    const int row_in = lane & 15;
    const int kh = lane >> 4;
    const int cc = ks * 2 + kh;            // 16B chunk index in k
    const uint32_t abase = sb + (uint32_t)s * STAGE_BYTES;
#pragma unroll
    for (int mi = 0; mi < 4; mi++) {
        int r = warp_m * 64 + mi * 16 + row_in;
        uint32_t addr = abase + (uint32_t)(r * 128) + (((uint32_t)cc ^ (uint32_t)(r & 7)) << 4);
        LDSM4(A[mi], addr);
    }
    const uint32_t bbase = abase + A_BYTES;
#pragma unroll
    for (int ni = 0; ni < 2; ni++) {
        int r = warp_n * 32 + ni * 16 + row_in;
        uint32_t addr = bbase + (uint32_t)(r * 128) + (((uint32_t)cc ^ (uint32_t)(r & 7)) << 4);
        LDSM4(B[ni], addr);
    }
}

__global__ void __launch_bounds__(NT, 2)
e8_gemm(const float* __restrict__ bias, float* __restrict__ out, int M, int N, int K)
{
    extern __shared__ char smem[];
    const uint32_t sb = smem_u32(smem);
    const int tid = threadIdx.x, lane = tid & 31, wid = tid >> 5;
    const int warp_m = wid & 1;            // 2 warp rows of 64
    const int warp_n = wid >> 1;           // 4 warp cols of 32
    const int NK = K / BK;

    // Rasterize: groups of 8 m-tiles, n fastest within group ->
    // wave working set stays L2-resident.
    const int n_tiles = N / BN;                    // 32
    const int bid = blockIdx.x;
    const int grp = bid / (n_tiles * 8);
    const int rem = bid % (n_tiles * 8);
    const int mt = grp * 8 + (rem & 7);
    const int nt = rem >> 3;
    const int m0 = mt * BM;
    const int n0 = nt * BN;

    const __half* gA = g_xh + (size_t)m0 * K;
    const __half* gB = g_q + (size_t)n0 * K;

    float c[4][4][4];
#pragma unroll
    for (int i = 0; i < 4; i++)
#pragma unroll
        for (int j = 0; j < 4; j++)
#pragma unroll
            for (int k = 0; k < 4; k++) c[i][j][k] = 0.f;

    // prologue: fill STAGES-1 stages
#pragma unroll
    for (int s = 0; s < STAGES - 1; s++) {
        load_stage(sb, s, s, tid, gA, gB, K);
        cp_commit();
    }

    uint32_t Af[4][4], Bf[2][4];
    int cur = 0;

    for (int kt = 0; kt < NK; kt++) {
        cp_wait<STAGES - 2>();
        __syncthreads();

        // Critical-path first: ks0 fragment loads go to the LSU BEFORE the
        // cp.async burst for the prefetch stage.
        lds_frags(sb, cur, 0, warp_m, warp_n, lane, Af, Bf);

        if (kt + STAGES - 1 < NK) {
            int nxt = cur + (STAGES - 1);
            if (nxt >= STAGES) nxt -= STAGES;
            load_stage(sb, nxt, kt + STAGES - 1, tid, gA, gB, K);
        }
        cp_commit();                                  // always commit: keeps group count aligned

#pragma unroll
        for (int ks = 0; ks < 4; ks++) {
            if (ks > 0)
                lds_frags(sb, cur, ks, warp_m, warp_n, lane, Af, Bf);
#pragma unroll
            for (int mi = 0; mi < 4; mi++) {
#pragma unroll
                for (int ni = 0; ni < 2; ni++) {
                    MMA16816(c[mi][ni * 2],     Af[mi], Bf[ni][0], Bf[ni][2]);
                    MMA16816(c[mi][ni * 2 + 1], Af[mi], Bf[ni][1], Bf[ni][3]);
                }
            }
        }
        cur++;
        if (cur >= STAGES) cur = 0;
    }

    // Epilogue: out = acc * scale[col] + bias[col]
    const int g = lane >> 2, t = lane & 3;
#pragma unroll
    for (int mi = 0; mi < 4; mi++) {
        const int r0 = m0 + warp_m * 64 + mi * 16 + g;
#pragma unroll
        for (int nj = 0; nj < 4; nj++) {
            const int col = n0 + warp_n * 32 + nj * 8 + t * 2;
            const float s0 = g_scale[col],     s1 = g_scale[col + 1];
            const float b0 = bias[col],        b1 = bias[col + 1];
            float2 v0 = make_float2(c[mi][nj][0] * s0 + b0, c[mi][nj][1] * s1 + b1);
            float2 v1 = make_float2(c[mi][nj][2] * s0 + b0, c[mi][nj][3] * s1 + b1);
            *(float2*)(out + (size_t)r0 * N + col) = v0;
            *(float2*)(out + (size_t)(r0 + 8) * N + col) = v1;
        }
    }
}

// ============================================================================
// Launch
// ============================================================================
extern "C" void kernel_launch(void* const* d_in, const int* in_sizes, int n_in,
                              void* d_out, int out_size) {
    (void)n_in; (void)out_size;
    const float* x    = (const float*)d_in[0];
    const float* w    = (const float*)d_in[1];
    const float* bias = (const float*)d_in[2];
    float* out = (float*)d_out;

    const int OUT = in_sizes[2];
    const int IN  = in_sizes[1] / OUT;
    const int B   = in_sizes[0] / IN;

    double adaptive = OUT / 10000.0;
    if (adaptive < 0.5) adaptive = 0.5;
    if (adaptive > 2.0) adaptive = 2.0;
    const float sf = (float)(60.0 * adaptive);

    prep_fused_kernel<<<OUT + XB, 256>>>(x, in_sizes[0], w, IN, OUT, sf);

    cudaFuncSetAttribute(e8_gemm, cudaFuncAttributeMaxDynamicSharedMemorySize, SMEM_TOTAL);
    const int grid = (B / BM) * (OUT / BN);
    e8_gemm<<<grid, NT, SMEM_TOTAL>>>(bias, out, B, OUT, IN);
}

// round 16
// speedup vs baseline: 1.1004x; 1.1004x over previous
#include <cuda_runtime.h>
#include <cuda_fp16.h>
#include <cstdint>
#include <cstddef>

// ============================================================================
// Static device scratch (allocation-free rule: __device__ globals)
// ============================================================================
#define MAXD 4096
__device__ __half g_xh[(size_t)MAXD * MAXD];   // x in fp16
__device__ __half g_q[(size_t)MAXD * MAXD];    // E8 lattice points q (exact in fp16)
__device__ float  g_scale[MAXD];               // row_norm_safe / sf

// ============================================================================
// PTX helpers (baseline sm_100: cp.async + ldmatrix + mma.sync)
// ============================================================================
static __device__ __forceinline__ uint32_t smem_u32(const void* p) {
    return (uint32_t)__cvta_generic_to_shared(p);
}
static __device__ __forceinline__ void cp_async16(uint32_t dst, const void* src) {
    asm volatile("cp.async.cg.shared.global [%0], [%1], 16;" :: "r"(dst), "l"(src));
}
static __device__ __forceinline__ void cp_commit() {
    asm volatile("cp.async.commit_group;");
}
template <int N>
static __device__ __forceinline__ void cp_wait() {
    asm volatile("cp.async.wait_group %0;" :: "n"(N));
}

#define LDSM4(R, addr) \
    asm volatile("ldmatrix.sync.aligned.m8n8.x4.shared.b16 {%0,%1,%2,%3}, [%4];" \
                 : "=r"((R)[0]), "=r"((R)[1]), "=r"((R)[2]), "=r"((R)[3]) : "r"(addr))

#define MMA16816(C, A, b0, b1) \
    asm volatile("mma.sync.aligned.m16n8k16.row.col.f32.f16.f16.f32 " \
                 "{%0,%1,%2,%3}, {%4,%5,%6,%7}, {%8,%9}, {%0,%1,%2,%3};" \
                 : "+f"((C)[0]), "+f"((C)[1]), "+f"((C)[2]), "+f"((C)[3]) \
                 : "r"((A)[0]), "r"((A)[1]), "r"((A)[2]), "r"((A)[3]), \
                   "r"(b0), "r"(b1))

// ============================================================================
// E8 lattice quantization (exactly matches the JAX reference semantics)
// ============================================================================
static __device__ __forceinline__ void nearest_d8(const float x[8], float y[8]) {
    float f[8], d[8];
    float s = 0.f;
#pragma unroll
    for (int i = 0; i < 8; i++) { f[i] = rintf(x[i]); d[i] = x[i] - f[i]; s += f[i]; }
    int odd = (int)(((long long)llrintf(s)) & 1);
    float amax = -1.f; int idx = 0;
#pragma unroll
    for (int i = 0; i < 8; i++) {
        float a = fabsf(d[i]);
        if (a > amax) { amax = a; idx = i; }   // strict > keeps FIRST max (jnp.argmax)
    }
#pragma unroll
    for (int i = 0; i < 8; i++) {
        float flip = (odd && (i == idx)) ? ((d[i] >= 0.f) ? 1.f : -1.f) : 0.f;
        y[i] = f[i] + flip;
    }
}

static __device__ __forceinline__ void e8_quant(const float x[8], float y[8]) {
    float y0[8], y1[8], xs[8];
    nearest_d8(x, y0);
#pragma unroll
    for (int i = 0; i < 8; i++) xs[i] = x[i] - 0.5f;
    nearest_d8(xs, y1);
#pragma unroll
    for (int i = 0; i < 8; i++) y1[i] += 0.5f;
    float d0 = 0.f, d1 = 0.f;
#pragma unroll
    for (int i = 0; i < 8; i++) {
        float a = x[i] - y0[i]; d0 += a * a;
        float b = x[i] - y1[i]; d1 += b * b;
    }
#pragma unroll
    for (int i = 0; i < 8; i++) y[i] = (d0 <= d1) ? y0[i] : y1[i];
}

// ============================================================================
// Fused prep kernel:
//   blocks [0, XB)       : x (fp32) -> fp16 into g_xh  (heavy blocks FIRST)
//   blocks [XB, XB+OUT)  : row norm (fp32 warp-reduce) + E8 quantize
// Vectorized: float4 loads + 16B packed half stores in the quant loop.
// ============================================================================
#define XB 1536

__global__ void prep_fused_kernel(const float* __restrict__ x, int nx,
                                  const float* __restrict__ w, int IN, int OUT,
                                  float sf)
{
    if ((int)blockIdx.x < XB) {
        // ---- x conversion part (runs first: 3x the per-block traffic) ----
        int i = blockIdx.x * blockDim.x + threadIdx.x;
        const int stride = XB * blockDim.x;
        const int n2 = nx >> 1;
        for (; i < n2; i += stride) {
            float2 v = ((const float2*)x)[i];
            ((__half2*)g_xh)[i] = __floats2half2_rn(v.x, v.y);
        }
        return;
    }

    const int row = blockIdx.x - XB;
    const float* wr = w + (size_t)row * IN;
    __shared__ float redf[8];
    __shared__ float s_inv;
    float part = 0.f;
    for (int i = threadIdx.x * 4; i < IN; i += blockDim.x * 4) {
        float4 t = *(const float4*)(wr + i);
        part += t.x * t.x + t.y * t.y + t.z * t.z + t.w * t.w;
    }
#pragma unroll
    for (int o = 16; o; o >>= 1) part += __shfl_xor_sync(0xffffffffu, part, o);
    if ((threadIdx.x & 31) == 0) redf[threadIdx.x >> 5] = part;
    __syncthreads();
    if (threadIdx.x == 0) {
        float t = 0.f;
        for (int i = 0; i < (int)(blockDim.x >> 5); i++) t += redf[i];
        float rn = sqrtf(t);
        rn = fmaxf(rn, 1e-8f);
        s_inv = sf / rn;               // one divide per row
        g_scale[row] = rn / sf;
    }
    __syncthreads();
    const float inv = s_inv;
    __half* qrow = g_q + (size_t)row * IN;
    const int nblk = IN >> 3;
    for (int b = threadIdx.x; b < nblk; b += blockDim.x) {
        float v[8], y[8];
        // vector loads: 2x float4 (32B) per 8-block
        float4 t0 = *(const float4*)(wr + b * 8);
        float4 t1 = *(const float4*)(wr + b * 8 + 4);
        v[0] = t0.x * inv; v[1] = t0.y * inv; v[2] = t0.z * inv; v[3] = t0.w * inv;
        v[4] = t1.x * inv; v[5] = t1.y * inv; v[6] = t1.z * inv; v[7] = t1.w * inv;
        e8_quant(v, y);
        // packed store: 8 halves = 16B in one STG.128
        __half2 h0 = __floats2half2_rn(y[0], y[1]);
        __half2 h1 = __floats2half2_rn(y[2], y[3]);
        __half2 h2 = __floats2half2_rn(y[4], y[5]);
        __half2 h3 = __floats2half2_rn(y[6], y[7]);
        uint4 pk;
        pk.x = *(uint32_t*)&h0; pk.y = *(uint32_t*)&h1;
        pk.z = *(uint32_t*)&h2; pk.w = *(uint32_t*)&h3;
        *(uint4*)(qrow + b * 8) = pk;
    }
}

// ============================================================================
// GEMM: out[M,N] = (x_fp16 @ q^T) * scale[n] + bias[n]
// BM=BN=128, BK=64, 256 threads (2x4 warps, 64x32 warp tiles), STAGES=3,
// 96KB smem/CTA -> 2 CTAs/SM. Exact R12 structure (fastest measured; the
// smem crossbar is 100% saturated at this tiling, scheduling tweaks regress).
// ============================================================================
#define BM 128
#define BN 128
#define BK 64
#define NT 256
#define STAGES 3
#define A_BYTES (BM * 128)                  // 16384
#define B_BYTES (BN * 128)                  // 16384
#define STAGE_BYTES (A_BYTES + B_BYTES)     // 32768
#define SMEM_TOTAL (STAGES * STAGE_BYTES)   // 98304

static __device__ __forceinline__ void load_stage(
    uint32_t sb, int s, int kt, int tid,
    const __half* gA, const __half* gB, int K)
{
    const int kc = kt * BK;                  // halves
    const uint32_t a = sb + (uint32_t)s * STAGE_BYTES;
    const uint32_t b = a + A_BYTES;
#pragma unroll
    for (int i = 0; i < (BM * 8) / NT; i++) {       // 4 iters
        int idx = tid + i * NT;
        int r = idx >> 3, cc = idx & 7;
        uint32_t off = (uint32_t)(r * 128 + (((uint32_t)cc ^ (uint32_t)(r & 7)) << 4));
        cp_async16(a + off, (const char*)(gA + (size_t)r * K + kc) + (cc << 4));
    }
#pragma unroll
    for (int i = 0; i < (BN * 8) / NT; i++) {       // 4 iters
        int idx = tid + i * NT;
        int r = idx >> 3, cc = idx & 7;
        uint32_t off = (uint32_t)(r * 128 + (((uint32_t)cc ^ (uint32_t)(r & 7)) << 4));
        cp_async16(b + off, (const char*)(gB + (size_t)r * K + kc) + (cc << 4));
    }
}

static __device__ __forceinline__ void lds_frags(
    uint32_t sb, int s, int ks, int warp_m, int warp_n, int lane,
    uint32_t A[4][4], uint32_t B[2][4])
{
    const int row_in = lane & 15;
    const int kh = lane >> 4;
    const int cc = ks * 2 + kh;            // 16B chunk index in k
    const uint32_t abase = sb + (uint32_t)s * STAGE_BYTES;
#pragma unroll
    for (int mi = 0; mi < 4; mi++) {
        int r = warp_m * 64 + mi * 16 + row_in;
        uint32_t addr = abase + (uint32_t)(r * 128) + (((uint32_t)cc ^ (uint32_t)(r & 7)) << 4);
        LDSM4(A[mi], addr);
    }
    const uint32_t bbase = abase + A_BYTES;
#pragma unroll
    for (int ni = 0; ni < 2; ni++) {
        int r = warp_n * 32 + ni * 16 + row_in;
        uint32_t addr = bbase + (uint32_t)(r * 128) + (((uint32_t)cc ^ (uint32_t)(r & 7)) << 4);
        LDSM4(B[ni], addr);
    }
}

__global__ void __launch_bounds__(NT, 2)
e8_gemm(const float* __restrict__ bias, float* __restrict__ out, int M, int N, int K)
{
    extern __shared__ char smem[];
    const uint32_t sb = smem_u32(smem);
    const int tid = threadIdx.x, lane = tid & 31, wid = tid >> 5;
    const int warp_m = wid & 1;            // 2 warp rows of 64
    const int warp_n = wid >> 1;           // 4 warp cols of 32
    const int NK = K / BK;

    // Rasterize: groups of 8 m-tiles, n fastest within group ->
    // wave working set stays L2-resident.
    const int n_tiles = N / BN;                    // 32
    const int bid = blockIdx.x;
    const int grp = bid / (n_tiles * 8);
    const int rem = bid % (n_tiles * 8);
    const int mt = grp * 8 + (rem & 7);
    const int nt = rem >> 3;
    const int m0 = mt * BM;
    const int n0 = nt * BN;

    const __half* gA = g_xh + (size_t)m0 * K;
    const __half* gB = g_q + (size_t)n0 * K;

    float c[4][4][4];
#pragma unroll
    for (int i = 0; i < 4; i++)
#pragma unroll
        for (int j = 0; j < 4; j++)
#pragma unroll
            for (int k = 0; k < 4; k++) c[i][j][k] = 0.f;

    // prologue: fill STAGES-1 stages
#pragma unroll
    for (int s = 0; s < STAGES - 1; s++) {
        load_stage(sb, s, s, tid, gA, gB, K);
        cp_commit();
    }

    uint32_t Af[4][4], Bf[2][4];
    int cur = 0;

    for (int kt = 0; kt < NK; kt++) {
        cp_wait<STAGES - 2>();
        __syncthreads();
        if (kt + STAGES - 1 < NK) {
            int nxt = cur + (STAGES - 1);
            if (nxt >= STAGES) nxt -= STAGES;
            load_stage(sb, nxt, kt + STAGES - 1, tid, gA, gB, K);
        }
        cp_commit();                                  // always commit: keeps group count aligned

#pragma unroll
        for (int ks = 0; ks < 4; ks++) {
            lds_frags(sb, cur, ks, warp_m, warp_n, lane, Af, Bf);
#pragma unroll
            for (int mi = 0; mi < 4; mi++) {
#pragma unroll
                for (int ni = 0; ni < 2; ni++) {
                    MMA16816(c[mi][ni * 2],     Af[mi], Bf[ni][0], Bf[ni][2]);
                    MMA16816(c[mi][ni * 2 + 1], Af[mi], Bf[ni][1], Bf[ni][3]);
                }
            }
        }
        cur++;
        if (cur >= STAGES) cur = 0;
    }

    // Epilogue: out = acc * scale[col] + bias[col]
    const int g = lane >> 2, t = lane & 3;
#pragma unroll
    for (int mi = 0; mi < 4; mi++) {
        const int r0 = m0 + warp_m * 64 + mi * 16 + g;
#pragma unroll
        for (int nj = 0; nj < 4; nj++) {
            const int col = n0 + warp_n * 32 + nj * 8 + t * 2;
            const float s0 = g_scale[col],     s1 = g_scale[col + 1];
            const float b0 = bias[col],        b1 = bias[col + 1];
            float2 v0 = make_float2(c[mi][nj][0] * s0 + b0, c[mi][nj][1] * s1 + b1);
            float2 v1 = make_float2(c[mi][nj][2] * s0 + b0, c[mi][nj][3] * s1 + b1);
            *(float2*)(out + (size_t)r0 * N + col) = v0;
            *(float2*)(out + (size_t)(r0 + 8) * N + col) = v1;
        }
    }
}

// ============================================================================
// Launch
// ============================================================================
extern "C" void kernel_launch(void* const* d_in, const int* in_sizes, int n_in,
                              void* d_out, int out_size) {
    (void)n_in; (void)out_size;
    const float* x    = (const float*)d_in[0];
    const float* w    = (const float*)d_in[1];
    const float* bias = (const float*)d_in[2];
    float* out = (float*)d_out;

    const int OUT = in_sizes[2];
    const int IN  = in_sizes[1] / OUT;
    const int B   = in_sizes[0] / IN;

    double adaptive = OUT / 10000.0;
    if (adaptive < 0.5) adaptive = 0.5;
    if (adaptive > 2.0) adaptive = 2.0;
    const float sf = (float)(60.0 * adaptive);

    prep_fused_kernel<<<XB + OUT, 256>>>(x, in_sizes[0], w, IN, OUT, sf);

    cudaFuncSetAttribute(e8_gemm, cudaFuncAttributeMaxDynamicSharedMemorySize, SMEM_TOTAL);
    const int grid = (B / BM) * (OUT / BN);
    e8_gemm<<<grid, NT, SMEM_TOTAL>>>(bias, out, B, OUT, IN);
}